// round 14
// baseline (speedup 1.0000x reference)
#include <cuda_runtime.h>

#define KNEI 8
#define EHID 16
// Persistent, software-pipelined kernel. 256 threads/block = 128 agents/tile,
// 2 threads per agent. Thread h of a pair owns neighbor slots {h,h+2,h+4,h+6}
// (row-interleaved: a lane pair's loads hit the SAME 128B line) and buffer
// slots {4h..4h+3}. Warps 0-1 fold the 4 mono nets ONCE per CTA, then the CTA
// loops over tiles, prefetching tile i+1's nei/ego loads before computing
// tile i (memory latency hides under the EX2/FMA compute of the current tile).

__device__ __forceinline__ float ex2f(float x) {
    float r; asm("ex2.approx.f32 %0, %1;" : "=f"(r) : "f"(x)); return r;
}
__device__ __forceinline__ float sqrt_apx(float x) {
    float r; asm("sqrt.approx.f32 %0, %1;" : "=f"(r) : "f"(x)); return r;
}

template <int NB>
__device__ __forceinline__ void mono_batch(const float2* __restrict__ terms,
                                           int nn, float bias,
                                           const float* __restrict__ x,
                                           float* __restrict__ y)
{
#pragma unroll
    for (int k = 0; k < NB; k++) y[k] = bias;
    for (int t = 0; t < nn; t++) {
        float2 wc = terms[t];
#pragma unroll
        for (int k = 0; k < NB; k++)
            y[k] = fmaf(wc.y, ex2f(wc.x * x[k]), y[k]);
    }
}

__device__ __forceinline__ float mono1(const float2* __restrict__ terms,
                                       int nn, float bias, float x)
{
    float y = bias;
    for (int t = 0; t < nn; t++) {
        float2 wc = terms[t];
        y = fmaf(wc.y, ex2f(wc.x * x), y);
    }
    return y;
}

__global__ void __launch_bounds__(256, 3)
sfm_main(const float* __restrict__ ego, const float* __restrict__ nei,
         const float* __restrict__ rec, float* __restrict__ out, int N,
         int numTiles,
         const float* __restrict__ rep_w1, const float* __restrict__ rep_b1,
         const float* __restrict__ rep_w2, const float* __restrict__ rep_b2,
         const float* __restrict__ att_w1, const float* __restrict__ att_b1,
         const float* __restrict__ att_w2, const float* __restrict__ att_b2,
         const float* __restrict__ bor_w1, const float* __restrict__ bor_b1,
         const float* __restrict__ bor_w2, const float* __restrict__ bor_b2,
         const float* __restrict__ del_w1, const float* __restrict__ del_b1,
         const float* __restrict__ del_w2, const float* __restrict__ del_b2,
         const float* __restrict__ p_dest, const float* __restrict__ angle,
         const float* __restrict__ border)
{
    __shared__ float2 sT[4][EHID];
    __shared__ float  sB[4];
    __shared__ int    sN[4];
    __shared__ float  sS[8];

    int t = threadIdx.x;
    int pid = t >> 1;          // pair (agent) index within tile
    int h   = t & 1;           // lane-in-pair
    const unsigned amask = 0xffffffffu;

    // ============ fold the 4 mono nets ONCE per CTA =======================
    if (t < 64) {
        int q = t >> 4, i = t & 15;
        int grp = (t & 31) >> 4;
        const float* w1 = (q==0)?rep_w1:(q==1)?att_w1:(q==2)?bor_w1:del_w1;
        const float* b1 = (q==0)?rep_b1:(q==1)?att_b1:(q==2)?bor_b1:del_b1;
        const float* w2 = (q==0)?rep_w2:(q==1)?att_w2:(q==2)?bor_w2:del_w2;
        const float* b2 = (q==0)?rep_b2:(q==1)?att_b2:(q==2)?bor_b2:del_b2;
        float wv  = w1[i];
        float ci  = w2[i] * expf(-b1[i]);
        float b2v = (i == 0) ? b2[0] : 0.0f;
        const float LOG2E = 1.4426950408889634f;
        bool pred = (wv != 0.0f);
        unsigned bal   = __ballot_sync(amask, pred);
        unsigned field = (bal >> (grp * 16)) & 0xFFFFu;
        int rank = __popc(field & ((1u << i) - 1u));
        if (pred) sT[q][rank] = make_float2(-wv * LOG2E, ci);
        float bz = pred ? 0.0f : ci;             // zero-weight terms -> bias
        bz += __shfl_xor_sync(amask, bz, 1);
        bz += __shfl_xor_sync(amask, bz, 2);
        bz += __shfl_xor_sync(amask, bz, 4);
        bz += __shfl_xor_sync(amask, bz, 8);
        if (i == 0) {
            sB[q] = bz + b2v;
            sN[q] = __popc(field);
        }
    } else if (t == 64) {
        sS[0] = 1.0f / p_dest[0];
        sS[1] = p_dest[1];
        float a = angle[0];
        sS[2] = a * a;
        sS[3] = border[0];
        sS[4] = border[3];
    }
    __syncthreads();   // the ONLY barrier; smem is read-only afterwards

    int tile = blockIdx.x;
    if (tile >= numTiles) return;

    // ============ preload first tile's nei + ego into registers ============
    float4 a4[4];
    float  vny[4];
    float4 e0, e1, e2, e3;
    {
        int nc = min(tile * 128 + pid, N - 1);
        const float* nb = nei + (size_t)nc * (KNEI * 16);
#pragma unroll
        for (int j = 0; j < 4; j++)
            a4[j] = *reinterpret_cast<const float4*>(nb + (size_t)(2 * j + h) * 16);
#pragma unroll
        for (int j = 0; j < 4; j++)
            vny[j] = __ldg(nb + (size_t)(2 * j + h) * 16 + 4);
        const float4* e4 = reinterpret_cast<const float4*>(ego) + (size_t)nc * 4;
        e0 = e4[0]; e1 = e4[1]; e2 = e4[2]; e3 = e4[3];
    }

    while (true) {
        int n  = tile * 128 + pid;
        int nc = min(n, N - 1);
        int nextTile = tile + gridDim.x;
        bool have = nextTile < numTiles;

        // ---- prefetch next tile (clamped; unconditional issue) ----
        float4 a4n[4];
        float  vnyn[4];
        float4 en0, en1, en2, en3;
        {
            int pt  = have ? nextTile : tile;
            int ncn = min(pt * 128 + pid, N - 1);
            const float* nbn = nei + (size_t)ncn * (KNEI * 16);
#pragma unroll
            for (int j = 0; j < 4; j++)
                a4n[j] = *reinterpret_cast<const float4*>(nbn + (size_t)(2 * j + h) * 16);
#pragma unroll
            for (int j = 0; j < 4; j++)
                vnyn[j] = __ldg(nbn + (size_t)(2 * j + h) * 16 + 4);
            const float4* e4n = reinterpret_cast<const float4*>(ego) + (size_t)ncn * 4;
            en0 = e4n[0]; en1 = e4n[1]; en2 = e4n[2]; en3 = e4n[3];
        }

        // ---- rec for current tile (consumers sit after the att/rep monos) -
        const float4* r4 = reinterpret_cast<const float4*>(rec) + (size_t)nc * 4;
        float4 rr0 = r4[2 * h], rr1 = r4[2 * h + 1];

        // ---- unpack ego ----
        float px = e0.y, py = e0.z;
        float vx = e0.w, vy = e1.x;
        float ids[8] = { e1.w, e2.x, e2.y, e2.z, e2.w, e3.x, e3.y, e3.z };

        // ---- geometry for own 4 neighbors ----
        bool  idxk[4];
        float rnv[4], bv[4], dxv[4], dyv[4];
#pragma unroll
        for (int j = 0; j < 4; j++) {
            float id = a4[j].x;
            bool m = false;
#pragma unroll
            for (int q = 0; q < 8; q++) m |= (id == ids[q]);
            bool ix = m && (id != 0.0f);
            idxk[j] = ix;

            float rx = a4[j].y - px, ry = a4[j].z - py;
            float s  = rx * rx + ry * ry;
            float ir = rsqrtf(s);
            float rn = s * ir;
            rnv[j] = rn;
            dxv[j] = rx * ir;
            dyv[j] = ry * ir;

            float vdx = a4[j].w * 0.02f, vdy = vny[j] * 0.02f;
            float tx = rx + vdx, ty = ry + vdy;
            float bb = rn + tx * tx + ty * ty - (vdx * vdx + vdy * vdy);
            bb = ix ? bb : 1.0f;
            bv[j] = sqrt_apx(fmaxf(bb, 1e-12f)) * 0.5f;
        }

        // ---- att / rep nets ----
        float att4[4], rep4[4];
        mono_batch<4>(sT[1], sN[1], sB[1], rnv, att4);
        mono_batch<4>(sT[0], sN[0], sB[0], bv,  rep4);

        // ---- exchange neighbor ids -> global-order nid8 ----
        float nidl[4] = { a4[0].x, a4[1].x, a4[2].x, a4[3].x };
        float nid8[8];
#pragma unroll
        for (int j = 0; j < 4; j++) {
            float o = __shfl_xor_sync(amask, nidl[j], 1);
            nid8[2 * j]     = h ? o       : nidl[j];
            nid8[2 * j + 1] = h ? nidl[j] : o;
        }

        // ---- buffer membership on own 4 buffer slots ----
        float bidl[4] = { rr0.x, rr0.z, rr1.x, rr1.z };
        float bctl[4] = { rr0.y, rr0.w, rr1.y, rr1.w };
        unsigned mown = 0;
#pragma unroll
        for (int i = 0; i < 4; i++) {
            bool f = false;
#pragma unroll
            for (int j = 0; j < 8; j++) f |= (bidl[i] == nid8[j]);
            mown |= (f ? 1u : 0u) << (4 * h + i);
        }
        unsigned m8 = mown | __shfl_xor_sync(amask, mown, 1);

        // ---- counts for own neighbor slots gi = 2i+h ----
        float countl[4];
        float del4[4];
        bool fast = __all_sync(amask, m8 == 0);
        if (fast) {
            // no buffer id matches any neighbor id -> every count is 1.0
            float du = mono1(sT[3], sN[3], sB[3], 1.0f);
#pragma unroll
            for (int j = 0; j < 4; j++) del4[j] = du;
        } else {
            // general path: exchange ct2 (buffer order) + stable rank-select
            float ct2l[4];
#pragma unroll
            for (int i = 0; i < 4; i++) {
                bool f = (mown >> (4 * h + i)) & 1u;
                ct2l[i] = bctl[i] + (f ? 1.0f : 0.0f);
            }
            float ct8[8];
#pragma unroll
            for (int i = 0; i < 4; i++) {
                float o = __shfl_xor_sync(amask, ct2l[i], 1);
                ct8[i]     = h ? o       : ct2l[i];
                ct8[4 + i] = h ? ct2l[i] : o;
            }
#pragma unroll
            for (int i = 0; i < 4; i++) {
                int gi = 2 * i + h;
                float ci = 1.0f;
                int seen = 0;
#pragma unroll
                for (int k = 0; k < 8; k++) {
                    bool b = (m8 >> k) & 1u;
                    bool take = b && (seen == gi);
                    ci = take ? ct8[k] : ci;
                    seen += b ? 1 : 0;
                }
                countl[i] = ci;
            }
            bool same = (countl[0] == countl[1]) & (countl[0] == countl[2]) &
                        (countl[0] == countl[3]);
            float oc0 = __shfl_xor_sync(amask, countl[0], 1);
            same = same && (countl[0] == oc0);
            if (__all_sync(amask, same)) {
                float du = mono1(sT[3], sN[3], sB[3], countl[0]);
#pragma unroll
                for (int j = 0; j < 4; j++) del4[j] = du;
            } else {
                mono_batch<4>(sT[3], sN[3], sB[3], countl, del4);
            }
        }

        float v2   = vx * vx + vy * vy;
        float ang2 = sS[2];

        // ---- neighbor forces (own 4), angle-clamped, then pair-reduce ----
        float fnx = 0.0f, fny = 0.0f;
#pragma unroll
        for (int j = 0; j < 4; j++) {
            bool ix = idxk[j];
            float da  = del4[j] * att4[j];
            float fax = ix ? da * dxv[j] : 0.0f;
            float fay = ix ? da * dyv[j] : 0.0f;
            float frx = ix ? rep4[j] * dxv[j] : 0.0f;
            float fry = ix ? rep4[j] * dyv[j] : 0.0f;

            float num = vx * fax + vy * fay;
            float nn  = fax * fax + fay * fay;
            bool keep = num * num > ang2 * fmaxf(v2 * nn, 1e-16f);
            fnx += keep ? fax : 0.0f;
            fny += keep ? fay : 0.0f;

            num  = vx * frx + vy * fry;
            nn   = frx * frx + fry * fry;
            keep = num * num > ang2 * fmaxf(v2 * nn, 1e-16f);
            fnx += keep ? frx : 0.0f;
            fny += keep ? fry : 0.0f;
        }
        fnx += __shfl_xor_sync(amask, fnx, 1);
        fny += __shfl_xor_sync(amask, fny, 1);

        // ---- border force: this thread handles border term h ----
        float bxc = e0.z;
        float rb  = bxc - sS[3 + h];
        float bm  = mono1(sT[2], sN[2], sB[2], fabsf(rb));
        float fv  = bm * copysignf(1.0f, rb);
        float fbyl = 0.0f;
        {
            float num = vy * fv, nn = fv * fv;
            if (num * num > ang2 * fmaxf(v2 * nn, 1e-16f)) fbyl = fv;
        }
        float fby = fbyl + __shfl_xor_sync(amask, fbyl, 1);

        // ---- destination force ----
        float speed = sqrt_apx(v2);
        float ip0 = sS[0], p1 = sS[1];
        float fdx = (p1 * speed - vx) * ip0;
        float fdy = (-vy) * ip0;
        {
            float num = vx * fdx + vy * fdy;
            float nn  = fdx * fdx + fdy * fdy;
            bool keep = num * num > ang2 * fmaxf(v2 * nn, 1e-16f);
            fdx = keep ? fdx : 0.0f;
            fdy = keep ? fdy : 0.0f;
        }

        // ---- output: (N, 3, 2); pair splits the 3 float2 stores ----
        if (n < N) {
            float2* o = reinterpret_cast<float2*>(out) + (size_t)n * 3;
            if (h == 0) {
                o[0] = make_float2(fdx, fdy);
                o[1] = make_float2(fnx, fny);
            } else {
                o[2] = make_float2(0.0f, fby);
            }
        }

        if (!have) break;
        tile = nextTile;
#pragma unroll
        for (int j = 0; j < 4; j++) { a4[j] = a4n[j]; vny[j] = vnyn[j]; }
        e0 = en0; e1 = en1; e2 = en2; e3 = en3;
    }
}

extern "C" void kernel_launch(void* const* d_in, const int* in_sizes, int n_in,
                              void* d_out, int out_size)
{
    const float* ego    = (const float*)d_in[0];
    const float* nei    = (const float*)d_in[1];
    const float* border = (const float*)d_in[2];
    const float* rec    = (const float*)d_in[3];
    const float* p_dest = (const float*)d_in[4];
    const float* angle  = (const float*)d_in[5];

    int N = in_sizes[0] / 16;
    int numTiles = (N + 127) / 128;             // 128 agents per tile
    int blocks = numTiles < 444 ? numTiles : 444;  // 148 SMs x occ 3, persistent
    sfm_main<<<blocks, 256>>>(
        ego, nei, rec, (float*)d_out, N, numTiles,
        (const float*)d_in[6],  (const float*)d_in[7],  (const float*)d_in[8],  (const float*)d_in[9],
        (const float*)d_in[10], (const float*)d_in[11], (const float*)d_in[12], (const float*)d_in[13],
        (const float*)d_in[14], (const float*)d_in[15], (const float*)d_in[16], (const float*)d_in[17],
        (const float*)d_in[18], (const float*)d_in[19], (const float*)d_in[20], (const float*)d_in[21],
        p_dest, angle, border);
}

// round 15
// speedup vs baseline: 1.0471x; 1.0471x over previous
#include <cuda_runtime.h>

#define KNEI 8
#define EHID 16
// Persistent grid-stride kernel. 256 threads/block = 128 agents per tile,
// 2 threads per agent. Thread h of a pair owns neighbor slots {h,h+2,h+4,h+6}
// (row-interleaved: a lane pair's loads hit the SAME 128B line) and buffer
// slots {4h..4h+3}. Warps 0-1 fold the 4 mono nets ONCE per CTA, then the CTA
// loops over tiles. Each iteration issues register-free prefetch.global.L2
// for the NEXT tile's lines, so the next iteration's LDGs are L2 hits.

__device__ __forceinline__ float ex2f(float x) {
    float r; asm("ex2.approx.f32 %0, %1;" : "=f"(r) : "f"(x)); return r;
}
__device__ __forceinline__ float sqrt_apx(float x) {
    float r; asm("sqrt.approx.f32 %0, %1;" : "=f"(r) : "f"(x)); return r;
}
__device__ __forceinline__ void pf_l2(const void* p) {
    asm volatile("prefetch.global.L2 [%0];" :: "l"(p));
}

template <int NB>
__device__ __forceinline__ void mono_batch(const float2* __restrict__ terms,
                                           int nn, float bias,
                                           const float* __restrict__ x,
                                           float* __restrict__ y)
{
#pragma unroll
    for (int k = 0; k < NB; k++) y[k] = bias;
    for (int t = 0; t < nn; t++) {
        float2 wc = terms[t];
#pragma unroll
        for (int k = 0; k < NB; k++)
            y[k] = fmaf(wc.y, ex2f(wc.x * x[k]), y[k]);
    }
}

__device__ __forceinline__ float mono1(const float2* __restrict__ terms,
                                       int nn, float bias, float x)
{
    float y = bias;
    for (int t = 0; t < nn; t++) {
        float2 wc = terms[t];
        y = fmaf(wc.y, ex2f(wc.x * x), y);
    }
    return y;
}

__global__ void __launch_bounds__(256, 4)
sfm_main(const float* __restrict__ ego, const float* __restrict__ nei,
         const float* __restrict__ rec, float* __restrict__ out, int N,
         int numTiles,
         const float* __restrict__ rep_w1, const float* __restrict__ rep_b1,
         const float* __restrict__ rep_w2, const float* __restrict__ rep_b2,
         const float* __restrict__ att_w1, const float* __restrict__ att_b1,
         const float* __restrict__ att_w2, const float* __restrict__ att_b2,
         const float* __restrict__ bor_w1, const float* __restrict__ bor_b1,
         const float* __restrict__ bor_w2, const float* __restrict__ bor_b2,
         const float* __restrict__ del_w1, const float* __restrict__ del_b1,
         const float* __restrict__ del_w2, const float* __restrict__ del_b2,
         const float* __restrict__ p_dest, const float* __restrict__ angle,
         const float* __restrict__ border)
{
    __shared__ float2 sT[4][EHID];
    __shared__ float  sB[4];
    __shared__ int    sN[4];
    __shared__ float  sS[8];

    int t = threadIdx.x;
    int pid = t >> 1;          // pair (agent) index within tile
    int h   = t & 1;           // lane-in-pair
    const unsigned amask = 0xffffffffu;

    // ============ fold the 4 mono nets ONCE per CTA =======================
    if (t < 64) {
        int q = t >> 4, i = t & 15;
        int grp = (t & 31) >> 4;
        const float* w1 = (q==0)?rep_w1:(q==1)?att_w1:(q==2)?bor_w1:del_w1;
        const float* b1 = (q==0)?rep_b1:(q==1)?att_b1:(q==2)?bor_b1:del_b1;
        const float* w2 = (q==0)?rep_w2:(q==1)?att_w2:(q==2)?bor_w2:del_w2;
        const float* b2 = (q==0)?rep_b2:(q==1)?att_b2:(q==2)?bor_b2:del_b2;
        float wv  = w1[i];
        float ci  = w2[i] * expf(-b1[i]);
        float b2v = (i == 0) ? b2[0] : 0.0f;
        const float LOG2E = 1.4426950408889634f;
        bool pred = (wv != 0.0f);
        unsigned bal   = __ballot_sync(amask, pred);
        unsigned field = (bal >> (grp * 16)) & 0xFFFFu;
        int rank = __popc(field & ((1u << i) - 1u));
        if (pred) sT[q][rank] = make_float2(-wv * LOG2E, ci);
        float bz = pred ? 0.0f : ci;             // zero-weight terms -> bias
        bz += __shfl_xor_sync(amask, bz, 1);
        bz += __shfl_xor_sync(amask, bz, 2);
        bz += __shfl_xor_sync(amask, bz, 4);
        bz += __shfl_xor_sync(amask, bz, 8);
        if (i == 0) {
            sB[q] = bz + b2v;
            sN[q] = __popc(field);
        }
    } else if (t == 64) {
        sS[0] = 1.0f / p_dest[0];
        sS[1] = p_dest[1];
        float a = angle[0];
        sS[2] = a * a;
        sS[3] = border[0];
        sS[4] = border[3];
    }
    __syncthreads();   // the ONLY barrier; smem is read-only afterwards

    // ============ persistent tile loop ============
    for (int tile = blockIdx.x; tile < numTiles; tile += gridDim.x) {
        int n  = tile * 128 + pid;
        int nc = min(n, N - 1);

        // ---- front-batched loads (current tile) ----
        const float* nb = nei + (size_t)nc * (KNEI * 16);
        float4 a4[4];
        float  vny[4];
#pragma unroll
        for (int j = 0; j < 4; j++)
            a4[j] = *reinterpret_cast<const float4*>(nb + (size_t)(2 * j + h) * 16);
#pragma unroll
        for (int j = 0; j < 4; j++)
            vny[j] = __ldg(nb + (size_t)(2 * j + h) * 16 + 4);  // same 32B sector

        const float4* e4 = reinterpret_cast<const float4*>(ego) + (size_t)nc * 4;
        float4 e0 = e4[0], e1 = e4[1], e2 = e4[2], e3 = e4[3];

        const float4* r4 = reinterpret_cast<const float4*>(rec) + (size_t)nc * 4;
        float4 rr0 = r4[2 * h], rr1 = r4[2 * h + 1];

        // ---- register-free L2 prefetch of the NEXT tile ----
        {
            int pt  = tile + gridDim.x;
            pt = (pt < numTiles) ? pt : tile;          // clamp: harmless re-touch
            int ncn = min(pt * 128 + pid, N - 1);
            const char* nbn = (const char*)nei + (size_t)ncn * 512;
            pf_l2(nbn + h * 256);                      // nei lines: pair covers
            pf_l2(nbn + h * 256 + 128);                //   all 4 x 128B lines
            pf_l2((const char*)ego + (size_t)ncn * 64);
            pf_l2((const char*)rec + (size_t)ncn * 64);
        }

        // ---- unpack ego ----
        float px = e0.y, py = e0.z;
        float vx = e0.w, vy = e1.x;
        float ids[8] = { e1.w, e2.x, e2.y, e2.z, e2.w, e3.x, e3.y, e3.z };

        // ---- geometry for own 4 neighbors ----
        bool  idxk[4];
        float rnv[4], bv[4], dxv[4], dyv[4];
#pragma unroll
        for (int j = 0; j < 4; j++) {
            float id = a4[j].x;
            bool m = false;
#pragma unroll
            for (int q = 0; q < 8; q++) m |= (id == ids[q]);
            bool ix = m && (id != 0.0f);
            idxk[j] = ix;

            float rx = a4[j].y - px, ry = a4[j].z - py;
            float s  = rx * rx + ry * ry;
            float ir = rsqrtf(s);
            float rn = s * ir;
            rnv[j] = rn;
            dxv[j] = rx * ir;
            dyv[j] = ry * ir;

            float vdx = a4[j].w * 0.02f, vdy = vny[j] * 0.02f;
            float tx = rx + vdx, ty = ry + vdy;
            float bb = rn + tx * tx + ty * ty - (vdx * vdx + vdy * vdy);
            bb = ix ? bb : 1.0f;
            bv[j] = sqrt_apx(fmaxf(bb, 1e-12f)) * 0.5f;
        }

        // ---- att / rep nets ----
        float att4[4], rep4[4];
        mono_batch<4>(sT[1], sN[1], sB[1], rnv, att4);
        mono_batch<4>(sT[0], sN[0], sB[0], bv,  rep4);

        // ---- exchange neighbor ids -> global-order nid8 ----
        float nidl[4] = { a4[0].x, a4[1].x, a4[2].x, a4[3].x };
        float nid8[8];
#pragma unroll
        for (int j = 0; j < 4; j++) {
            float o = __shfl_xor_sync(amask, nidl[j], 1);
            nid8[2 * j]     = h ? o       : nidl[j];
            nid8[2 * j + 1] = h ? nidl[j] : o;
        }

        // ---- buffer membership on own 4 buffer slots ----
        float bidl[4] = { rr0.x, rr0.z, rr1.x, rr1.z };
        float bctl[4] = { rr0.y, rr0.w, rr1.y, rr1.w };
        unsigned mown = 0;
#pragma unroll
        for (int i = 0; i < 4; i++) {
            bool f = false;
#pragma unroll
            for (int j = 0; j < 8; j++) f |= (bidl[i] == nid8[j]);
            mown |= (f ? 1u : 0u) << (4 * h + i);
        }
        unsigned m8 = mown | __shfl_xor_sync(amask, mown, 1);

        // ---- counts for own neighbor slots gi = 2i+h ----
        float countl[4];
        float del4[4];
        bool fast = __all_sync(amask, m8 == 0);
        if (fast) {
            // no buffer id matches any neighbor id -> every count is 1.0
            float du = mono1(sT[3], sN[3], sB[3], 1.0f);
#pragma unroll
            for (int j = 0; j < 4; j++) del4[j] = du;
        } else {
            // general path: exchange ct2 (buffer order) + stable rank-select
            float ct2l[4];
#pragma unroll
            for (int i = 0; i < 4; i++) {
                bool f = (mown >> (4 * h + i)) & 1u;
                ct2l[i] = bctl[i] + (f ? 1.0f : 0.0f);
            }
            float ct8[8];
#pragma unroll
            for (int i = 0; i < 4; i++) {
                float o = __shfl_xor_sync(amask, ct2l[i], 1);
                ct8[i]     = h ? o       : ct2l[i];
                ct8[4 + i] = h ? ct2l[i] : o;
            }
#pragma unroll
            for (int i = 0; i < 4; i++) {
                int gi = 2 * i + h;
                float ci = 1.0f;
                int seen = 0;
#pragma unroll
                for (int k = 0; k < 8; k++) {
                    bool b = (m8 >> k) & 1u;
                    bool take = b && (seen == gi);
                    ci = take ? ct8[k] : ci;
                    seen += b ? 1 : 0;
                }
                countl[i] = ci;
            }
            bool same = (countl[0] == countl[1]) & (countl[0] == countl[2]) &
                        (countl[0] == countl[3]);
            float oc0 = __shfl_xor_sync(amask, countl[0], 1);
            same = same && (countl[0] == oc0);
            if (__all_sync(amask, same)) {
                float du = mono1(sT[3], sN[3], sB[3], countl[0]);
#pragma unroll
                for (int j = 0; j < 4; j++) del4[j] = du;
            } else {
                mono_batch<4>(sT[3], sN[3], sB[3], countl, del4);
            }
        }

        float v2   = vx * vx + vy * vy;
        float ang2 = sS[2];

        // ---- neighbor forces (own 4), angle-clamped, then pair-reduce ----
        float fnx = 0.0f, fny = 0.0f;
#pragma unroll
        for (int j = 0; j < 4; j++) {
            bool ix = idxk[j];
            float da  = del4[j] * att4[j];
            float fax = ix ? da * dxv[j] : 0.0f;
            float fay = ix ? da * dyv[j] : 0.0f;
            float frx = ix ? rep4[j] * dxv[j] : 0.0f;
            float fry = ix ? rep4[j] * dyv[j] : 0.0f;

            float num = vx * fax + vy * fay;
            float nn  = fax * fax + fay * fay;
            bool keep = num * num > ang2 * fmaxf(v2 * nn, 1e-16f);
            fnx += keep ? fax : 0.0f;
            fny += keep ? fay : 0.0f;

            num  = vx * frx + vy * fry;
            nn   = frx * frx + fry * fry;
            keep = num * num > ang2 * fmaxf(v2 * nn, 1e-16f);
            fnx += keep ? frx : 0.0f;
            fny += keep ? fry : 0.0f;
        }
        fnx += __shfl_xor_sync(amask, fnx, 1);
        fny += __shfl_xor_sync(amask, fny, 1);

        // ---- border force: this thread handles border term h ----
        float bxc = e0.z;
        float rb  = bxc - sS[3 + h];
        float bm  = mono1(sT[2], sN[2], sB[2], fabsf(rb));
        float fv  = bm * copysignf(1.0f, rb);
        float fbyl = 0.0f;
        {
            float num = vy * fv, nn = fv * fv;
            if (num * num > ang2 * fmaxf(v2 * nn, 1e-16f)) fbyl = fv;
        }
        float fby = fbyl + __shfl_xor_sync(amask, fbyl, 1);

        // ---- destination force ----
        float speed = sqrt_apx(v2);
        float ip0 = sS[0], p1 = sS[1];
        float fdx = (p1 * speed - vx) * ip0;
        float fdy = (-vy) * ip0;
        {
            float num = vx * fdx + vy * fdy;
            float nn  = fdx * fdx + fdy * fdy;
            bool keep = num * num > ang2 * fmaxf(v2 * nn, 1e-16f);
            fdx = keep ? fdx : 0.0f;
            fdy = keep ? fdy : 0.0f;
        }

        // ---- output: (N, 3, 2); pair splits the 3 float2 stores ----
        if (n < N) {
            float2* o = reinterpret_cast<float2*>(out) + (size_t)n * 3;
            if (h == 0) {
                o[0] = make_float2(fdx, fdy);
                o[1] = make_float2(fnx, fny);
            } else {
                o[2] = make_float2(0.0f, fby);
            }
        }
    }
}

extern "C" void kernel_launch(void* const* d_in, const int* in_sizes, int n_in,
                              void* d_out, int out_size)
{
    const float* ego    = (const float*)d_in[0];
    const float* nei    = (const float*)d_in[1];
    const float* border = (const float*)d_in[2];
    const float* rec    = (const float*)d_in[3];
    const float* p_dest = (const float*)d_in[4];
    const float* angle  = (const float*)d_in[5];

    int N = in_sizes[0] / 16;
    int numTiles = (N + 127) / 128;                // 128 agents per tile
    int blocks = numTiles < 592 ? numTiles : 592;  // 148 SMs x occ 4, persistent
    sfm_main<<<blocks, 256>>>(
        ego, nei, rec, (float*)d_out, N, numTiles,
        (const float*)d_in[6],  (const float*)d_in[7],  (const float*)d_in[8],  (const float*)d_in[9],
        (const float*)d_in[10], (const float*)d_in[11], (const float*)d_in[12], (const float*)d_in[13],
        (const float*)d_in[14], (const float*)d_in[15], (const float*)d_in[16], (const float*)d_in[17],
        (const float*)d_in[18], (const float*)d_in[19], (const float*)d_in[20], (const float*)d_in[21],
        p_dest, angle, border);
}

// round 16
// speedup vs baseline: 1.1676x; 1.1150x over previous
#include <cuda_runtime.h>

#define KNEI 8
#define EHID 16
// Persistent grid-stride kernel. 256 threads/block = 128 agents per tile,
// 2 threads per agent. Thread h of a pair owns neighbor slots {h,h+2,h+4,h+6}
// (row-interleaved: a lane pair's loads hit the SAME 128B line) and buffer
// slots {4h..4h+3}. Warps 0-1 fold the 4 mono nets ONCE per CTA
// (ballot-rank compaction, one __syncthreads), then the CTA loops over tiles.
// Angle clamp uses the magnitude-invariance identity: for f = c*d the keep
// decision reduces to (v.r)^2 > ang^2 v^2 |r|^2, so att+rep share ONE clamp
// and the border clamp is just vy^2 > ang^2 v^2.

__device__ __forceinline__ float ex2f(float x) {
    float r; asm("ex2.approx.f32 %0, %1;" : "=f"(r) : "f"(x)); return r;
}
__device__ __forceinline__ float sqrt_apx(float x) {
    float r; asm("sqrt.approx.f32 %0, %1;" : "=f"(r) : "f"(x)); return r;
}

template <int NB>
__device__ __forceinline__ void mono_batch(const float2* __restrict__ terms,
                                           int nn, float bias,
                                           const float* __restrict__ x,
                                           float* __restrict__ y)
{
#pragma unroll
    for (int k = 0; k < NB; k++) y[k] = bias;
    for (int t = 0; t < nn; t++) {
        float2 wc = terms[t];
#pragma unroll
        for (int k = 0; k < NB; k++)
            y[k] = fmaf(wc.y, ex2f(wc.x * x[k]), y[k]);
    }
}

// two-accumulator version: halves the dependent FMA/EX2 chain latency
__device__ __forceinline__ float mono1(const float2* __restrict__ terms,
                                       int nn, float bias, float x)
{
    float y0 = bias, y1 = 0.0f;
    int t = 0;
    for (; t + 1 < nn; t += 2) {
        float2 a = terms[t];
        float2 b = terms[t + 1];
        y0 = fmaf(a.y, ex2f(a.x * x), y0);
        y1 = fmaf(b.y, ex2f(b.x * x), y1);
    }
    if (t < nn) {
        float2 a = terms[t];
        y0 = fmaf(a.y, ex2f(a.x * x), y0);
    }
    return y0 + y1;
}

__global__ void __launch_bounds__(256, 4)
sfm_main(const float* __restrict__ ego, const float* __restrict__ nei,
         const float* __restrict__ rec, float* __restrict__ out, int N,
         int numTiles,
         const float* __restrict__ rep_w1, const float* __restrict__ rep_b1,
         const float* __restrict__ rep_w2, const float* __restrict__ rep_b2,
         const float* __restrict__ att_w1, const float* __restrict__ att_b1,
         const float* __restrict__ att_w2, const float* __restrict__ att_b2,
         const float* __restrict__ bor_w1, const float* __restrict__ bor_b1,
         const float* __restrict__ bor_w2, const float* __restrict__ bor_b2,
         const float* __restrict__ del_w1, const float* __restrict__ del_b1,
         const float* __restrict__ del_w2, const float* __restrict__ del_b2,
         const float* __restrict__ p_dest, const float* __restrict__ angle,
         const float* __restrict__ border)
{
    __shared__ float2 sT[4][EHID];
    __shared__ float  sB[4];
    __shared__ int    sN[4];
    __shared__ float  sS[8];

    int t = threadIdx.x;
    int pid = t >> 1;          // pair (agent) index within tile
    int h   = t & 1;           // lane-in-pair
    const unsigned amask = 0xffffffffu;

    // ============ fold the 4 mono nets ONCE per CTA =======================
    if (t < 64) {
        int q = t >> 4, i = t & 15;
        int grp = (t & 31) >> 4;
        const float* w1 = (q==0)?rep_w1:(q==1)?att_w1:(q==2)?bor_w1:del_w1;
        const float* b1 = (q==0)?rep_b1:(q==1)?att_b1:(q==2)?bor_b1:del_b1;
        const float* w2 = (q==0)?rep_w2:(q==1)?att_w2:(q==2)?bor_w2:del_w2;
        const float* b2 = (q==0)?rep_b2:(q==1)?att_b2:(q==2)?bor_b2:del_b2;
        float wv  = w1[i];
        float ci  = w2[i] * expf(-b1[i]);
        float b2v = (i == 0) ? b2[0] : 0.0f;
        const float LOG2E = 1.4426950408889634f;
        bool pred = (wv != 0.0f);
        unsigned bal   = __ballot_sync(amask, pred);
        unsigned field = (bal >> (grp * 16)) & 0xFFFFu;
        int rank = __popc(field & ((1u << i) - 1u));
        if (pred) sT[q][rank] = make_float2(-wv * LOG2E, ci);
        float bz = pred ? 0.0f : ci;             // zero-weight terms -> bias
        bz += __shfl_xor_sync(amask, bz, 1);
        bz += __shfl_xor_sync(amask, bz, 2);
        bz += __shfl_xor_sync(amask, bz, 4);
        bz += __shfl_xor_sync(amask, bz, 8);
        if (i == 0) {
            sB[q] = bz + b2v;
            sN[q] = __popc(field);
        }
    } else if (t == 64) {
        sS[0] = 1.0f / p_dest[0];
        sS[1] = p_dest[1];
        float a = angle[0];
        sS[2] = a * a;
        sS[3] = border[0];
        sS[4] = border[3];
    }
    __syncthreads();   // the ONLY barrier; smem is read-only afterwards

    // ============ persistent tile loop ============
    for (int tile = blockIdx.x; tile < numTiles; tile += gridDim.x) {
        int n  = tile * 128 + pid;
        int nc = min(n, N - 1);

        // ---- front-batched loads ----
        const float* nb = nei + (size_t)nc * (KNEI * 16);
        float4 a4[4];
        float  vny[4];
#pragma unroll
        for (int j = 0; j < 4; j++)
            a4[j] = *reinterpret_cast<const float4*>(nb + (size_t)(2 * j + h) * 16);
#pragma unroll
        for (int j = 0; j < 4; j++)
            vny[j] = __ldg(nb + (size_t)(2 * j + h) * 16 + 4);  // same 32B sector

        const float4* e4 = reinterpret_cast<const float4*>(ego) + (size_t)nc * 4;
        float4 e0 = e4[0], e1 = e4[1], e2 = e4[2], e3 = e4[3];

        const float4* r4 = reinterpret_cast<const float4*>(rec) + (size_t)nc * 4;
        float4 rr0 = r4[2 * h], rr1 = r4[2 * h + 1];

        // ---- unpack ego ----
        float px = e0.y, py = e0.z;
        float vx = e0.w, vy = e1.x;
        float ids[8] = { e1.w, e2.x, e2.y, e2.z, e2.w, e3.x, e3.y, e3.z };

        float v2   = vx * vx + vy * vy;
        float ang2 = sS[2];
        float a2v2 = ang2 * v2;          // shared clamp threshold

        // ---- geometry + magnitude-invariant clamp for own 4 neighbors ----
        bool  usek[4];                    // idx && angle-keep, both per-slot
        float rnv[4], bv[4], dxv[4], dyv[4];
#pragma unroll
        for (int j = 0; j < 4; j++) {
            float id = a4[j].x;
            bool m = false;
#pragma unroll
            for (int q = 0; q < 8; q++) m |= (id == ids[q]);
            bool ix = m && (id != 0.0f);

            float rx = a4[j].y - px, ry = a4[j].z - py;
            float s  = rx * rx + ry * ry;
            float ir = rsqrtf(s);
            float rn = s * ir;
            rnv[j] = rn;
            dxv[j] = rx * ir;
            dyv[j] = ry * ir;

            // keep decision is magnitude-invariant: (v.r)^2 > ang^2 v^2 |r|^2
            float vr = vx * rx + vy * ry;
            usek[j] = ix && (vr * vr > a2v2 * s);

            float vdx = a4[j].w * 0.02f, vdy = vny[j] * 0.02f;
            float tx = rx + vdx, ty = ry + vdy;
            float bb = rn + tx * tx + ty * ty - (vdx * vdx + vdy * vdy);
            bb = ix ? bb : 1.0f;
            bv[j] = sqrt_apx(fmaxf(bb, 1e-12f)) * 0.5f;
        }

        // ---- att / rep nets ----
        float att4[4], rep4[4];
        mono_batch<4>(sT[1], sN[1], sB[1], rnv, att4);
        mono_batch<4>(sT[0], sN[0], sB[0], bv,  rep4);

        // ---- exchange neighbor ids -> global-order nid8 ----
        float nidl[4] = { a4[0].x, a4[1].x, a4[2].x, a4[3].x };
        float nid8[8];
#pragma unroll
        for (int j = 0; j < 4; j++) {
            float o = __shfl_xor_sync(amask, nidl[j], 1);
            nid8[2 * j]     = h ? o       : nidl[j];
            nid8[2 * j + 1] = h ? nidl[j] : o;
        }

        // ---- buffer membership on own 4 buffer slots ----
        float bidl[4] = { rr0.x, rr0.z, rr1.x, rr1.z };
        float bctl[4] = { rr0.y, rr0.w, rr1.y, rr1.w };
        unsigned mown = 0;
#pragma unroll
        for (int i = 0; i < 4; i++) {
            bool f = false;
#pragma unroll
            for (int j = 0; j < 8; j++) f |= (bidl[i] == nid8[j]);
            mown |= (f ? 1u : 0u) << (4 * h + i);
        }
        unsigned m8 = mown | __shfl_xor_sync(amask, mown, 1);

        // ---- counts for own neighbor slots gi = 2i+h ----
        float countl[4];
        float del4[4];
        bool fast = __all_sync(amask, m8 == 0);
        if (fast) {
            // no buffer id matches any neighbor id -> every count is 1.0
            float du = mono1(sT[3], sN[3], sB[3], 1.0f);
#pragma unroll
            for (int j = 0; j < 4; j++) del4[j] = du;
        } else {
            // general path: exchange ct2 (buffer order) + stable rank-select
            float ct2l[4];
#pragma unroll
            for (int i = 0; i < 4; i++) {
                bool f = (mown >> (4 * h + i)) & 1u;
                ct2l[i] = bctl[i] + (f ? 1.0f : 0.0f);
            }
            float ct8[8];
#pragma unroll
            for (int i = 0; i < 4; i++) {
                float o = __shfl_xor_sync(amask, ct2l[i], 1);
                ct8[i]     = h ? o       : ct2l[i];
                ct8[4 + i] = h ? ct2l[i] : o;
            }
#pragma unroll
            for (int i = 0; i < 4; i++) {
                int gi = 2 * i + h;
                float ci = 1.0f;
                int seen = 0;
#pragma unroll
                for (int k = 0; k < 8; k++) {
                    bool b = (m8 >> k) & 1u;
                    bool take = b && (seen == gi);
                    ci = take ? ct8[k] : ci;
                    seen += b ? 1 : 0;
                }
                countl[i] = ci;
            }
            bool same = (countl[0] == countl[1]) & (countl[0] == countl[2]) &
                        (countl[0] == countl[3]);
            float oc0 = __shfl_xor_sync(amask, countl[0], 1);
            same = same && (countl[0] == oc0);
            if (__all_sync(amask, same)) {
                float du = mono1(sT[3], sN[3], sB[3], countl[0]);
#pragma unroll
                for (int j = 0; j < 4; j++) del4[j] = du;
            } else {
                mono_batch<4>(sT[3], sN[3], sB[3], countl, del4);
            }
        }

        // ---- neighbor forces: ONE clamp for att+rep, pair-reduce ----
        float fnx = 0.0f, fny = 0.0f;
#pragma unroll
        for (int j = 0; j < 4; j++) {
            float c = fmaf(del4[j], att4[j], rep4[j]);   // da + rep
            bool u = usek[j];
            fnx += u ? c * dxv[j] : 0.0f;
            fny += u ? c * dyv[j] : 0.0f;
        }
        fnx += __shfl_xor_sync(amask, fnx, 1);
        fny += __shfl_xor_sync(amask, fny, 1);

        // ---- border force: keep is just vy^2 > ang^2 v^2 ----
        float bxc = e0.z;
        float rb  = bxc - sS[3 + h];
        float bm  = mono1(sT[2], sN[2], sB[2], fabsf(rb));
        float fv  = bm * copysignf(1.0f, rb);
        bool  kb  = (vy * vy > a2v2);
        float fbyl = kb ? fv : 0.0f;
        float fby = fbyl + __shfl_xor_sync(amask, fbyl, 1);

        // ---- destination force (direction not a scalar multiple: full form)
        float speed = sqrt_apx(v2);
        float ip0 = sS[0], p1 = sS[1];
        float fdx = (p1 * speed - vx) * ip0;
        float fdy = (-vy) * ip0;
        {
            float num = vx * fdx + vy * fdy;
            float nn  = fdx * fdx + fdy * fdy;
            bool keep = num * num > ang2 * fmaxf(v2 * nn, 1e-16f);
            fdx = keep ? fdx : 0.0f;
            fdy = keep ? fdy : 0.0f;
        }

        // ---- output: (N, 3, 2); pair splits the 3 float2 stores ----
        if (n < N) {
            float2* o = reinterpret_cast<float2*>(out) + (size_t)n * 3;
            if (h == 0) {
                o[0] = make_float2(fdx, fdy);
                o[1] = make_float2(fnx, fny);
            } else {
                o[2] = make_float2(0.0f, fby);
            }
        }
    }
}

extern "C" void kernel_launch(void* const* d_in, const int* in_sizes, int n_in,
                              void* d_out, int out_size)
{
    const float* ego    = (const float*)d_in[0];
    const float* nei    = (const float*)d_in[1];
    const float* border = (const float*)d_in[2];
    const float* rec    = (const float*)d_in[3];
    const float* p_dest = (const float*)d_in[4];
    const float* angle  = (const float*)d_in[5];

    int N = in_sizes[0] / 16;
    int numTiles = (N + 127) / 128;                // 128 agents per tile
    int blocks = numTiles < 592 ? numTiles : 592;  // 148 SMs x occ 4, persistent
    sfm_main<<<blocks, 256>>>(
        ego, nei, rec, (float*)d_out, N, numTiles,
        (const float*)d_in[6],  (const float*)d_in[7],  (const float*)d_in[8],  (const float*)d_in[9],
        (const float*)d_in[10], (const float*)d_in[11], (const float*)d_in[12], (const float*)d_in[13],
        (const float*)d_in[14], (const float*)d_in[15], (const float*)d_in[16], (const float*)d_in[17],
        (const float*)d_in[18], (const float*)d_in[19], (const float*)d_in[20], (const float*)d_in[21],
        p_dest, angle, border);
}